// round 1
// baseline (speedup 1.0000x reference)
#include <cuda_runtime.h>

// Trilinear resample, zero boundary (niftyreg interpolation=1, boundary=0).
// inputs:      [B=2, X=144, Y=144, Z=144, C=2] fp32
// deformation: [B, X, Y, Z, 3] fp32, absolute voxel coords per axis
// output:      [B, X, Y, Z, C] fp32

#define SX 144
#define SY 144
#define SZ 144
#define NC 2

__global__ __launch_bounds__(256) void resample_trilinear_zero(
    const float* __restrict__ inp,
    const float* __restrict__ def,
    float* __restrict__ out,
    int total)  // total = B * SX * SY * SZ
{
    int idx = blockIdx.x * blockDim.x + threadIdx.x;
    if (idx >= total) return;

    // b = idx / (SX*SY*SZ); spatial decomposition only needed for batch.
    const int vol = SX * SY * SZ;
    int b = idx / vol;

    // Coalesced deformation read: 3 consecutive floats per thread.
    const float* d = def + (size_t)idx * 3;
    float cx = __ldg(d + 0);
    float cy = __ldg(d + 1);
    float cz = __ldg(d + 2);

    float fx = floorf(cx), fy = floorf(cy), fz = floorf(cz);
    int ix0 = (int)fx, iy0 = (int)fy, iz0 = (int)fz;
    float tx = cx - fx, ty = cy - fy, tz = cz - fz;

    float wx[2] = {1.0f - tx, tx};
    float wy[2] = {1.0f - ty, ty};
    float wz[2] = {1.0f - tz, tz};

    const float* base = inp + (size_t)b * vol * NC;

    float acc0 = 0.0f, acc1 = 0.0f;

#pragma unroll
    for (int dx = 0; dx < 2; dx++) {
        int ix = ix0 + dx;
        bool vx = (ix >= 0) && (ix < SX);
        int cxp = min(max(ix, 0), SX - 1);
#pragma unroll
        for (int dy = 0; dy < 2; dy++) {
            int iy = iy0 + dy;
            bool vxy = vx && (iy >= 0) && (iy < SY);
            int cyp = min(max(iy, 0), SY - 1);
            float wxy = wx[dx] * wy[dy];
            const float* row = base + ((size_t)cxp * SY + cyp) * (size_t)SZ * NC;
#pragma unroll
            for (int dz = 0; dz < 2; dz++) {
                int iz = iz0 + dz;
                bool v = vxy && (iz >= 0) && (iz < SZ);
                int czp = min(max(iz, 0), SZ - 1);
                // 2 channels contiguous: one 8-byte load per corner.
                float2 val = __ldg((const float2*)(row + (size_t)czp * NC));
                float w = v ? (wxy * wz[dz]) : 0.0f;
                acc0 = fmaf(w, val.x, acc0);
                acc1 = fmaf(w, val.y, acc1);
            }
        }
    }

    // Coalesced float2 store.
    ((float2*)out)[idx] = make_float2(acc0, acc1);
}

extern "C" void kernel_launch(void* const* d_in, const int* in_sizes, int n_in,
                              void* d_out, int out_size)
{
    int total = out_size / NC;  // B*X*Y*Z voxels

    // Identify inputs by size: deformation has 3*total elements, image 2*total.
    const float* inp = (const float*)d_in[0];
    const float* def = (const float*)d_in[1];
    if (n_in >= 2) {
        long long t = (long long)total;
        if ((long long)in_sizes[0] == 3LL * t && (long long)in_sizes[1] == 2LL * t) {
            def = (const float*)d_in[0];
            inp = (const float*)d_in[1];
        }
    }

    const int threads = 256;
    int blocks = (total + threads - 1) / threads;
    resample_trilinear_zero<<<blocks, threads>>>(inp, def, (float*)d_out, total);
}

// round 2
// speedup vs baseline: 1.0544x; 1.0544x over previous
#include <cuda_runtime.h>

// Trilinear resample, zero boundary (niftyreg interpolation=1, boundary=0).
// inputs:      [B=2, X=144, Y=144, Z=144, C=2] fp32
// deformation: [B, X, Y, Z, 3] fp32, absolute voxel coords per axis
// output:      [B, X, Y, Z, C] fp32

#define SX 144
#define SY 144
#define SZ 144
#define NC 2
#define VOL (SX * SY * SZ)

__global__ __launch_bounds__(256) void resample_trilinear_zero(
    const float* __restrict__ inp,
    const float* __restrict__ def,
    float* __restrict__ out,
    int total)
{
    int idx = blockIdx.x * blockDim.x + threadIdx.x;
    if (idx >= total) return;

    int b = idx / VOL;

    // Coalesced deformation read: 3 consecutive floats per thread.
    const float* d = def + (size_t)idx * 3;
    float cx = __ldg(d + 0);
    float cy = __ldg(d + 1);
    float cz = __ldg(d + 2);

    float fx = floorf(cx), fy = floorf(cy), fz = floorf(cz);
    int ix0 = (int)fx, iy0 = (int)fy, iz0 = (int)fz;
    float tx = cx - fx, ty = cy - fy, tz = cz - fz;

    float wx[2] = {1.0f - tx, tx};
    float wy[2] = {1.0f - ty, ty};
    float wz0 = 1.0f - tz, wz1 = tz;

    // z handling (shared by all 4 xy corners):
    //  fast path: both z corners in range AND iz0 even -> one aligned float4.
    //  slow path: two clamped float2 loads with per-z zeroed weights.
    bool z_both_in = (iz0 >= 0) & (iz0 + 1 < SZ);
    bool z_f4      = z_both_in & ((iz0 & 1) == 0);
    int  zc0 = min(max(iz0, 0), SZ - 1);
    int  zc1 = min(max(iz0 + 1, 0), SZ - 1);
    float gz0 = (iz0 >= 0 && iz0 < SZ) ? wz0 : 0.0f;
    float gz1 = (iz0 + 1 >= 0 && iz0 + 1 < SZ) ? wz1 : 0.0f;

    const float* base = inp + (unsigned)b * (unsigned)(VOL * NC);

    float acc0 = 0.0f, acc1 = 0.0f;

#pragma unroll
    for (int dx = 0; dx < 2; dx++) {
        int ix = ix0 + dx;
        bool vx = (ix >= 0) & (ix < SX);
        unsigned cxp = (unsigned)min(max(ix, 0), SX - 1);
#pragma unroll
        for (int dy = 0; dy < 2; dy++) {
            int iy = iy0 + dy;
            bool vxy = vx & (iy >= 0) & (iy < SY);
            unsigned cyp = (unsigned)min(max(iy, 0), SY - 1);
            float wxy = vxy ? (wx[dx] * wy[dy]) : 0.0f;

            const float* row = base + (cxp * SY + cyp) * (SZ * NC);

            float v0, v1;
            if (z_f4) {
                // 16B-aligned load covering both z corners (2 ch each).
                float4 v = __ldg((const float4*)(row + (unsigned)iz0 * NC));
                v0 = fmaf(v.x, wz0, v.z * wz1);
                v1 = fmaf(v.y, wz0, v.w * wz1);
            } else {
                float2 a = __ldg((const float2*)(row + (unsigned)zc0 * NC));
                float2 c = __ldg((const float2*)(row + (unsigned)zc1 * NC));
                v0 = fmaf(a.x, gz0, c.x * gz1);
                v1 = fmaf(a.y, gz0, c.y * gz1);
            }
            acc0 = fmaf(wxy, v0, acc0);
            acc1 = fmaf(wxy, v1, acc1);
        }
    }

    // Coalesced float2 store.
    ((float2*)out)[idx] = make_float2(acc0, acc1);
}

extern "C" void kernel_launch(void* const* d_in, const int* in_sizes, int n_in,
                              void* d_out, int out_size)
{
    int total = out_size / NC;  // B*X*Y*Z voxels

    // Identify inputs by size: deformation has 3*total elements, image 2*total.
    const float* inp = (const float*)d_in[0];
    const float* def = (const float*)d_in[1];
    if (n_in >= 2) {
        long long t = (long long)total;
        if ((long long)in_sizes[0] == 3LL * t && (long long)in_sizes[1] == 2LL * t) {
            def = (const float*)d_in[0];
            inp = (const float*)d_in[1];
        }
    }

    const int threads = 256;
    int blocks = (total + threads - 1) / threads;
    resample_trilinear_zero<<<blocks, threads>>>(inp, def, (float*)d_out, total);
}